// round 2
// baseline (speedup 1.0000x reference)
#include <cuda_runtime.h>
#include <math.h>

#define Bv   256
#define SXv  34
#define SYv  34
#define H1   512
#define H2   1024
#define IND  66
#define OD   65
#define VV   64
#define BIG_NEG -1000000000.0f

// ---------------- device scratch (static, no allocations) ----------------
__device__ float g_hf[2][Bv][H1];
__device__ float g_cf[Bv][H1];
__device__ float g_hr[2][Bv][H1];
__device__ float g_cr[Bv][H1];
__device__ float g_hm[2][Bv][H2];
__device__ float g_cm[Bv][H2];
__device__ float g_xemb[SXv][Bv][2*H1];   // [i][b][1024] fwd|bwd
__device__ float g_yemb[SYv][Bv][H2];     // [j][b][1024]
__device__ int   g_toks[SXv][Bv];
__device__ int   g_tokt[SYv][Bv];
__device__ float g_lx[2][SXv][OD][Bv];    // [head][i][o][b]  head0=sub head1=ins
__device__ float g_ly[2][SYv][OD][Bv];

__device__ __forceinline__ float sigm(float x){ return 1.0f/(1.0f+expf(-x)); }

// ---------------- init: zero states + tokenize one-hots ----------------
__global__ void init_kernel(const float* __restrict__ src, const float* __restrict__ tgt)
{
    int idx = blockIdx.x * blockDim.x + threadIdx.x;
    if (idx < Bv*H1) {
        ((float*)g_hf)[idx] = 0.f; ((float*)g_cf)[idx] = 0.f;
        ((float*)g_hr)[idx] = 0.f; ((float*)g_cr)[idx] = 0.f;
    }
    if (idx < Bv*H2) {
        ((float*)g_hm)[idx] = 0.f; ((float*)g_cm)[idx] = 0.f;
    }
    if (idx < SXv*Bv) {
        const float* p = src + (long)idx * IND;
        int tok = -1;
        #pragma unroll 1
        for (int v = 0; v < IND; v++) if (p[v] > 0.5f) tok = v;
        ((int*)g_toks)[idx] = tok;
        const float* q = tgt + (long)idx * IND;
        tok = -1;
        #pragma unroll 1
        for (int v = 0; v < IND; v++) if (q[v] > 0.5f) tok = v;
        ((int*)g_tokt)[idx] = tok;
    }
}

// ---------------- fused 3-LSTM recurrent step ----------------
// grid 512 blocks: [0,128) fwd, [128,256) rev, [256,512) modern
// block tile: 32 batch x 32 hidden units (=> 128 gate rows), K = HID
__global__ __launch_bounds__(256) void lstm_step(int t,
    const float* __restrict__ WhhF, const float* __restrict__ WihF, const float* __restrict__ bF,
    const float* __restrict__ WhhR, const float* __restrict__ WihR, const float* __restrict__ bR,
    const float* __restrict__ WhhM, const float* __restrict__ WihM, const float* __restrict__ bM)
{
    __shared__ float hS[32][33];
    __shared__ float wS[128][33];
    __shared__ float gateS[4][32][33];

    const int blk = blockIdx.x;
    const int tid = threadIdx.x;
    const int cur = t & 1;

    int HID, bl, ostride, ooff;
    const float *Whh, *Wih, *bias, *hprev;
    float *hnext, *cbuf, *outp;
    const int *tok;

    if (blk < 128) {
        bl = blk; HID = H1; Whh = WhhF; Wih = WihF; bias = bF;
        hprev = &g_hf[cur][0][0]; hnext = &g_hf[cur^1][0][0]; cbuf = &g_cf[0][0];
        tok = &g_toks[t][0];
        outp = &g_xemb[t][0][0]; ostride = 2*H1; ooff = 0;
    } else if (blk < 256) {
        bl = blk - 128; HID = H1; Whh = WhhR; Wih = WihR; bias = bR;
        hprev = &g_hr[cur][0][0]; hnext = &g_hr[cur^1][0][0]; cbuf = &g_cr[0][0];
        tok = &g_toks[SXv-1-t][0];
        outp = &g_xemb[SXv-1-t][0][0]; ostride = 2*H1; ooff = H1;
    } else {
        bl = blk - 256; HID = H2; Whh = WhhM; Wih = WihM; bias = bM;
        hprev = &g_hm[cur][0][0]; hnext = &g_hm[cur^1][0][0]; cbuf = &g_cm[0][0];
        tok = &g_tokt[t][0];
        outp = &g_yemb[t][0][0]; ostride = H2; ooff = 0;
    }
    const int b0 = (bl & 7) * 32;
    const int h0 = (bl >> 3) * 32;

    const int bx = tid & 7;      // batch group (4 rows)
    const int gx = tid >> 3;     // gate-row group (4 rows)
    const int lrow = tid >> 3;   // load row 0..31
    const int k4 = (tid & 7) << 2;

    float acc[4][4];
    #pragma unroll
    for (int i = 0; i < 4; i++)
        #pragma unroll
        for (int j = 0; j < 4; j++) acc[i][j] = 0.f;

    for (int k0 = 0; k0 < HID; k0 += 32) {
        float4 hv = *(const float4*)&hprev[(b0+lrow)*HID + k0 + k4];
        hS[lrow][k4+0]=hv.x; hS[lrow][k4+1]=hv.y; hS[lrow][k4+2]=hv.z; hS[lrow][k4+3]=hv.w;
        #pragma unroll
        for (int li = 0; li < 4; li++) {
            int gl = lrow + (li << 5);
            int q = gl >> 5, hh = gl & 31;
            float4 wv = *(const float4*)&Whh[(q*HID + h0 + hh)*HID + k0 + k4];
            wS[gl][k4+0]=wv.x; wS[gl][k4+1]=wv.y; wS[gl][k4+2]=wv.z; wS[gl][k4+3]=wv.w;
        }
        __syncthreads();
        #pragma unroll
        for (int kk = 0; kk < 32; kk++) {
            float hr[4], wr[4];
            #pragma unroll
            for (int i = 0; i < 4; i++) hr[i] = hS[bx*4+i][kk];
            #pragma unroll
            for (int j = 0; j < 4; j++) wr[j] = wS[gx*4+j][kk];
            #pragma unroll
            for (int i = 0; i < 4; i++)
                #pragma unroll
                for (int j = 0; j < 4; j++)
                    acc[i][j] += hr[i]*wr[j];
        }
        __syncthreads();
    }

    // add one-hot input projection (column gather of Wih) + bias, stage gates
    int toks4[4];
    #pragma unroll
    for (int i = 0; i < 4; i++) toks4[i] = tok[b0 + bx*4 + i];

    #pragma unroll
    for (int j = 0; j < 4; j++) {
        int gl = gx*4 + j; int q = gl >> 5; int hh = gl & 31;
        int row = q*HID + h0 + hh;
        float bb = bias[row];
        #pragma unroll
        for (int i = 0; i < 4; i++) {
            float gin = bb + (toks4[i] >= 0 ? Wih[row*IND + toks4[i]] : 0.f);
            gateS[q][hh][bx*4+i] = acc[i][j] + gin;
        }
    }
    __syncthreads();

    // pointwise LSTM cell update: 1024 (b,hh) pairs / 256 threads
    #pragma unroll
    for (int u = 0; u < 4; u++) {
        int idx = tid + u*256;
        int b_l = idx & 31; int hh = idx >> 5;
        float gi = gateS[0][hh][b_l];
        float gf = gateS[1][hh][b_l];
        float gg = gateS[2][hh][b_l];
        float go = gateS[3][hh][b_l];
        int b = b0 + b_l; int h = h0 + hh;
        float cn = sigm(gf)*cbuf[b*HID+h] + sigm(gi)*tanhf(gg);
        float hn = sigm(go)*tanhf(cn);
        cbuf[b*HID+h]  = cn;
        hnext[b*HID+h] = hn;
        outp[b*ostride + ooff + h] = hn;
    }
}

// ---------------- head projections: lx / ly, both heads fused ----------------
// grid (272, 2): 272 row-tiles of 32 over 34*256 rows; y=0 -> x_emb->lx, y=1 -> y_emb->ly(+bias)
__global__ __launch_bounds__(256) void heads_kernel(
    const float* __restrict__ Wsub, const float* __restrict__ bsub,
    const float* __restrict__ Wins, const float* __restrict__ bins)
{
    __shared__ float xS[32][33];
    __shared__ float wS[130][33];

    const int rowblk = blockIdx.x;
    const int srcsel = blockIdx.y;
    const int tid = threadIdx.x;
    const int row0 = rowblk * 32;

    const float* X = srcsel ? &g_yemb[0][0][0] : &g_xemb[0][0][0];
    float* dst = srcsel ? &g_ly[0][0][0][0] : &g_lx[0][0][0][0];

    const int bx = tid & 7, ox = tid >> 3;
    const int lr = tid >> 3, k4 = (tid & 7) << 2;

    float acc[4][5];
    #pragma unroll
    for (int i = 0; i < 4; i++)
        #pragma unroll
        for (int u = 0; u < 5; u++) acc[i][u] = 0.f;

    for (int k0 = 0; k0 < H2; k0 += 32) {
        float4 xv = *(const float4*)&X[(row0+lr)*H2 + k0 + k4];
        xS[lr][k4+0]=xv.x; xS[lr][k4+1]=xv.y; xS[lr][k4+2]=xv.z; xS[lr][k4+3]=xv.w;
        #pragma unroll
        for (int li = 0; li < 5; li++) {
            int gl = lr + li*32;
            if (gl < 2*OD) {
                const float* W = (gl < OD) ? &Wsub[gl*H2] : &Wins[(gl-OD)*H2];
                float4 wv = *(const float4*)&W[k0 + k4];
                wS[gl][k4+0]=wv.x; wS[gl][k4+1]=wv.y; wS[gl][k4+2]=wv.z; wS[gl][k4+3]=wv.w;
            }
        }
        __syncthreads();
        #pragma unroll
        for (int kk = 0; kk < 32; kk++) {
            float xr[4];
            #pragma unroll
            for (int i = 0; i < 4; i++) xr[i] = xS[bx*4+i][kk];
            #pragma unroll
            for (int u = 0; u < 5; u++) {
                int o = ox + 32*u;
                float wr = (o < 2*OD) ? wS[o][kk] : 0.f;
                #pragma unroll
                for (int i = 0; i < 4; i++) acc[i][u] += xr[i]*wr;
            }
        }
        __syncthreads();
    }

    #pragma unroll
    for (int u = 0; u < 5; u++) {
        int o = ox + 32*u;
        if (o >= 2*OD) continue;
        int head = (o >= OD) ? 1 : 0;
        int oo = o - head*OD;
        float bterm = srcsel ? (head ? bins[oo] : bsub[oo]) : 0.f;
        #pragma unroll
        for (int i = 0; i < 4; i++) {
            int r = row0 + bx*4 + i;
            int iseq = r >> 8, b = r & 255;
            dst[((head*SXv + iseq)*OD + oo)*Bv + b] = acc[i][u] + bterm;
        }
    }
}

// ---------------- pair logsumexp + masked gathers -> output ----------------
// grid 34*34 blocks, 256 threads = batch
__global__ __launch_bounds__(256) void pairs_kernel(float* __restrict__ out)
{
    const int i = blockIdx.x / SYv;
    const int j = blockIdx.x % SYv;
    const int b = threadIdx.x;

    const bool x_any = g_toks[i][b] >= 0;
    const bool y_any = g_tokt[j][b] >= 0;
    const bool valid = x_any && y_any && (j < SYv-1);
    const int tnext = (j+1 < SYv) ? g_tokt[j+1][b] : -1;
    const bool ins_ok = valid && (tnext != IND-1);

    const float* lx0 = &g_lx[0][i][0][0];
    const float* lx1 = &g_lx[1][i][0][0];
    const float* ly0 = &g_ly[0][j][0][0];
    const float* ly1 = &g_ly[1][j][0][0];

    float m0 = -1e30f, s0 = 0.f, m1 = -1e30f, s1 = 0.f;
    #pragma unroll 1
    for (int o = 0; o < OD; o++) {
        float z0 = lx0[o*Bv+b] + ly0[o*Bv+b];
        float nm0 = fmaxf(m0, z0);
        s0 = s0*__expf(m0-nm0) + __expf(z0-nm0);
        m0 = nm0;
        float z1 = lx1[o*Bv+b] + ly1[o*Bv+b];
        float nm1 = fmaxf(m1, z1);
        s1 = s1*__expf(m1-nm1) + __expf(z1-nm1);
        m1 = nm1;
    }
    const float lse0 = m0 + __logf(s0);   // sub head
    const float lse1 = m1 + __logf(s1);   // ins head

    float dlt  = valid ? (lx0[VV*Bv+b] + ly0[VV*Bv+b] - lse0) : BIG_NEG;
    float endv = valid ? (lx1[VV*Bv+b] + ly1[VV*Bv+b] - lse1) : BIG_NEG;
    float insv = BIG_NEG, subv = BIG_NEG;
    if (ins_ok) {
        if (tnext >= 0 && tnext < VV) {
            subv = lx0[tnext*Bv+b] + ly0[tnext*Bv+b] - lse0;
            insv = lx1[tnext*Bv+b] + ly1[tnext*Bv+b] - lse1;
        } else {
            insv = 0.f; subv = 0.f;   // one-hot dot with zero row
        }
    }

    const int base  = (i*SYv + j)*Bv + b;
    const int plane = SXv*SYv*Bv;
    out[0*plane + base] = insv;
    out[1*plane + base] = subv;
    out[2*plane + base] = endv;
    out[3*plane + base] = dlt;
}

// ---------------- launch ----------------
extern "C" void kernel_launch(void* const* d_in, const int* in_sizes, int n_in,
                              void* d_out, int out_size)
{
    const float* sources = (const float*)d_in[0];
    const float* targets = (const float*)d_in[1];
    const float* Wih_f = (const float*)d_in[2];
    const float* Whh_f = (const float*)d_in[3];
    const float* b_f   = (const float*)d_in[4];
    const float* Wih_r = (const float*)d_in[5];
    const float* Whh_r = (const float*)d_in[6];
    const float* b_r   = (const float*)d_in[7];
    const float* Wih_m = (const float*)d_in[8];
    const float* Whh_m = (const float*)d_in[9];
    const float* b_m   = (const float*)d_in[10];
    const float* W_sub = (const float*)d_in[11];
    const float* b_sub = (const float*)d_in[12];
    const float* W_ins = (const float*)d_in[13];
    const float* b_ins = (const float*)d_in[14];
    float* out = (float*)d_out;

    init_kernel<<<1024, 256>>>(sources, targets);
    for (int t = 0; t < SXv; t++) {
        lstm_step<<<512, 256>>>(t, Whh_f, Wih_f, b_f,
                                   Whh_r, Wih_r, b_r,
                                   Whh_m, Wih_m, b_m);
    }
    heads_kernel<<<dim3(272, 2), 256>>>(W_sub, b_sub, W_ins, b_ins);
    pairs_kernel<<<SXv*SYv, 256>>>(out);
}

// round 3
// speedup vs baseline: 1.8201x; 1.8201x over previous
#include <cuda_runtime.h>
#include <math.h>

#define Bv   256
#define SXv  34
#define SYv  34
#define H1   512
#define H2   1024
#define IND  66
#define OD   65
#define VV   64
#define BIG_NEG -1000000000.0f
#define PAD  132

// ---------------- device scratch (static, no allocations) ----------------
__device__ float g_hf[2][Bv][H1];
__device__ float g_cf[Bv][H1];
__device__ float g_hr[2][Bv][H1];
__device__ float g_cr[Bv][H1];
__device__ float g_hm[2][Bv][H2];
__device__ float g_cm[Bv][H2];
__device__ float g_xemb[SXv][Bv][2*H1];   // [i][b][1024] fwd|bwd
__device__ float g_yemb[SYv][Bv][H2];     // [j][b][1024]
__device__ int   g_toks[SXv][Bv];
__device__ int   g_tokt[SYv][Bv];
__device__ float g_lx[2][SXv][OD][Bv];    // [head][i][o][b]  head0=sub head1=ins
__device__ float g_ly[2][SYv][OD][Bv];

__device__ __forceinline__ float sigm(float x){ return 1.0f/(1.0f+expf(-x)); }

#define LDS_V2U64(a,b,addr) \
    asm volatile("ld.shared.v2.u64 {%0,%1},[%2];" : "=l"(a),"=l"(b) : "r"(addr))
#define DUP2(d,x) \
    asm("mov.b64 %0,{%1,%1};" : "=l"(d) : "f"(x))
#define FMA2(acc,a,b) \
    asm("fma.rn.f32x2 %0,%2,%3,%0;" : "+l"(acc) : "l"(acc),"l"(a),"l"(b))
#define UNPACK2(lo,hi,v) \
    asm("mov.b64 {%0,%1},%2;" : "=f"(lo),"=f"(hi) : "l"(v))

// ---------------- init: zero states + tokenize one-hots ----------------
__global__ void init_kernel(const float* __restrict__ src, const float* __restrict__ tgt)
{
    int idx = blockIdx.x * blockDim.x + threadIdx.x;
    if (idx < Bv*H1) {
        ((float*)g_hf)[idx] = 0.f; ((float*)g_cf)[idx] = 0.f;
        ((float*)g_hr)[idx] = 0.f; ((float*)g_cr)[idx] = 0.f;
    }
    if (idx < Bv*H2) {
        ((float*)g_hm)[idx] = 0.f; ((float*)g_cm)[idx] = 0.f;
    }
    if (idx < SXv*Bv) {
        const float* p = src + (long)idx * IND;
        int tok = -1;
        #pragma unroll 1
        for (int v = 0; v < IND; v++) if (p[v] > 0.5f) tok = v;
        ((int*)g_toks)[idx] = tok;
        const float* q = tgt + (long)idx * IND;
        tok = -1;
        #pragma unroll 1
        for (int v = 0; v < IND; v++) if (q[v] > 0.5f) tok = v;
        ((int*)g_tokt)[idx] = tok;
    }
}

// ---------------- fused 3-LSTM recurrent step (FFMA2, 128 blocks single wave) ----
// blocks: [0,32) fwd, [32,64) rev, [64,128) modern
// block tile: 128 gate-rows (32 h-units x 4 gates) x 128 batch, K = HID
// thread (tx=tid&15 batch-8, ty=tid>>4 h-unit-pair): 8 gate rows x 8 batch,
// gate rows packed in pairs (gate q, h-units 2ty / 2ty+1) -> f32x2 accumulators.
__global__ __launch_bounds__(256, 1) void lstm_step(int t,
    const float* __restrict__ WhhF, const float* __restrict__ WihF, const float* __restrict__ bF,
    const float* __restrict__ WhhR, const float* __restrict__ WihR, const float* __restrict__ bR,
    const float* __restrict__ WhhM, const float* __restrict__ WihM, const float* __restrict__ bM)
{
    __shared__ float hS[32][PAD];   // [k][batch]
    __shared__ float wS[32][PAD];   // [k][permuted gate row c = ty*8 + q*2 + p]

    const int blk = blockIdx.x;
    const int tid = threadIdx.x;
    const int cur = t & 1;

    int HID, bl, ostride, ooff;
    const float *Whh, *Wih, *bias, *hprev;
    float *hnext, *cbuf, *outp;
    const int *tok;

    if (blk < 32) {
        bl = blk; HID = H1; Whh = WhhF; Wih = WihF; bias = bF;
        hprev = &g_hf[cur][0][0]; hnext = &g_hf[cur^1][0][0]; cbuf = &g_cf[0][0];
        tok = &g_toks[t][0];
        outp = &g_xemb[t][0][0]; ostride = 2*H1; ooff = 0;
    } else if (blk < 64) {
        bl = blk - 32; HID = H1; Whh = WhhR; Wih = WihR; bias = bR;
        hprev = &g_hr[cur][0][0]; hnext = &g_hr[cur^1][0][0]; cbuf = &g_cr[0][0];
        tok = &g_toks[SXv-1-t][0];
        outp = &g_xemb[SXv-1-t][0][0]; ostride = 2*H1; ooff = H1;
    } else {
        bl = blk - 64; HID = H2; Whh = WhhM; Wih = WihM; bias = bM;
        hprev = &g_hm[cur][0][0]; hnext = &g_hm[cur^1][0][0]; cbuf = &g_cm[0][0];
        tok = &g_tokt[t][0];
        outp = &g_yemb[t][0][0]; ostride = H2; ooff = 0;
    }
    const int b0 = (bl & 1) * 128;
    const int h0 = (bl >> 1) * 32;

    const int tx = tid & 15;     // batch group of 8
    const int ty = tid >> 4;     // h-unit pair

    // loader decomposition (same for h and w): id = tid + s*256, row/c = id>>3, kq = id&7
    const int lrow = tid >> 3;        // 0..31 base row for s=0
    const int lkq  = tid & 7;

    unsigned long long acc[4][8];
    #pragma unroll
    for (int q = 0; q < 4; q++)
        #pragma unroll
        for (int i = 0; i < 8; i++) acc[q][i] = 0ULL;

    const unsigned hbase = (unsigned)__cvta_generic_to_shared(&hS[0][0]);
    const unsigned wbase = (unsigned)__cvta_generic_to_shared(&wS[0][0]);

    float4 ph[4], pw[4];
    // prefetch chunk 0
    #pragma unroll
    for (int s = 0; s < 4; s++) {
        int row = lrow + s*32;
        ph[s] = *(const float4*)&hprev[(size_t)(b0+row)*HID + lkq*4];
        int c = row;
        int q = (c >> 1) & 3, p = c & 1, tyy = c >> 3;
        int grow = q*HID + h0 + 2*tyy + p;
        pw[s] = *(const float4*)&Whh[(size_t)grow*HID + lkq*4];
    }

    const int nch = HID >> 5;
    for (int ch = 0; ch < nch; ch++) {
        // commit prefetched chunk to smem (transposed to k-major)
        #pragma unroll
        for (int s = 0; s < 4; s++) {
            int row = lrow + s*32;
            hS[lkq*4+0][row] = ph[s].x; hS[lkq*4+1][row] = ph[s].y;
            hS[lkq*4+2][row] = ph[s].z; hS[lkq*4+3][row] = ph[s].w;
            wS[lkq*4+0][row] = pw[s].x; wS[lkq*4+1][row] = pw[s].y;
            wS[lkq*4+2][row] = pw[s].z; wS[lkq*4+3][row] = pw[s].w;
        }
        __syncthreads();

        // prefetch next chunk while computing
        if (ch + 1 < nch) {
            int k0 = (ch + 1) << 5;
            #pragma unroll
            for (int s = 0; s < 4; s++) {
                int row = lrow + s*32;
                ph[s] = *(const float4*)&hprev[(size_t)(b0+row)*HID + k0 + lkq*4];
                int c = row;
                int q = (c >> 1) & 3, p = c & 1, tyy = c >> 3;
                int grow = q*HID + h0 + 2*tyy + p;
                pw[s] = *(const float4*)&Whh[(size_t)grow*HID + k0 + lkq*4];
            }
        }

        #pragma unroll 8
        for (int kk = 0; kk < 32; kk++) {
            unsigned waddr = wbase + (unsigned)((kk*PAD + ty*8) * 4);
            unsigned long long wp0, wp1, wp2, wp3;
            LDS_V2U64(wp0, wp1, waddr);
            LDS_V2U64(wp2, wp3, waddr + 16);

            const float4 hv0 = *(const float4*)((const char*)0 + 0, &hS[kk][tx*8]);
            const float4 hv1 = *(const float4*)&hS[kk][tx*8 + 4];
            unsigned long long hd[8];
            DUP2(hd[0], hv0.x); DUP2(hd[1], hv0.y);
            DUP2(hd[2], hv0.z); DUP2(hd[3], hv0.w);
            DUP2(hd[4], hv1.x); DUP2(hd[5], hv1.y);
            DUP2(hd[6], hv1.z); DUP2(hd[7], hv1.w);

            #pragma unroll
            for (int i = 0; i < 8; i++) {
                FMA2(acc[0][i], wp0, hd[i]);
                FMA2(acc[1][i], wp1, hd[i]);
                FMA2(acc[2][i], wp2, hd[i]);
                FMA2(acc[3][i], wp3, hd[i]);
            }
        }
        __syncthreads();
    }

    // ---- epilogue: per-thread full LSTM cell update for 2 h-units x 8 batches ----
    #pragma unroll
    for (int i = 0; i < 8; i++) {
        const int b = b0 + tx*8 + i;
        const int tk = tok[b];
        float glo[4], ghi[4];
        UNPACK2(glo[0], ghi[0], acc[0][i]);
        UNPACK2(glo[1], ghi[1], acc[1][i]);
        UNPACK2(glo[2], ghi[2], acc[2][i]);
        UNPACK2(glo[3], ghi[3], acc[3][i]);
        #pragma unroll
        for (int p = 0; p < 2; p++) {
            const int hg = h0 + 2*ty + p;
            float gv[4];
            #pragma unroll
            for (int q = 0; q < 4; q++) {
                int row = q*HID + hg;
                float add = bias[row] + (tk >= 0 ? Wih[row*IND + tk] : 0.f);
                gv[q] = (p ? ghi[q] : glo[q]) + add;
            }
            float cprev = cbuf[(size_t)b*HID + hg];
            float cn = sigm(gv[1])*cprev + sigm(gv[0])*tanhf(gv[2]);
            float hn = sigm(gv[3])*tanhf(cn);
            cbuf[(size_t)b*HID + hg]  = cn;
            hnext[(size_t)b*HID + hg] = hn;
            outp[(size_t)b*ostride + ooff + hg] = hn;
        }
    }
}

// ---------------- head projections: lx / ly, both heads fused ----------------
__global__ __launch_bounds__(256) void heads_kernel(
    const float* __restrict__ Wsub, const float* __restrict__ bsub,
    const float* __restrict__ Wins, const float* __restrict__ bins)
{
    __shared__ float xS[32][33];
    __shared__ float wS[130][33];

    const int rowblk = blockIdx.x;
    const int srcsel = blockIdx.y;
    const int tid = threadIdx.x;
    const int row0 = rowblk * 32;

    const float* X = srcsel ? &g_yemb[0][0][0] : &g_xemb[0][0][0];
    float* dst = srcsel ? &g_ly[0][0][0][0] : &g_lx[0][0][0][0];

    const int bx = tid & 7, ox = tid >> 3;
    const int lr = tid >> 3, k4 = (tid & 7) << 2;

    float acc[4][5];
    #pragma unroll
    for (int i = 0; i < 4; i++)
        #pragma unroll
        for (int u = 0; u < 5; u++) acc[i][u] = 0.f;

    for (int k0 = 0; k0 < H2; k0 += 32) {
        float4 xv = *(const float4*)&X[(row0+lr)*H2 + k0 + k4];
        xS[lr][k4+0]=xv.x; xS[lr][k4+1]=xv.y; xS[lr][k4+2]=xv.z; xS[lr][k4+3]=xv.w;
        #pragma unroll
        for (int li = 0; li < 5; li++) {
            int gl = lr + li*32;
            if (gl < 2*OD) {
                const float* W = (gl < OD) ? &Wsub[gl*H2] : &Wins[(gl-OD)*H2];
                float4 wv = *(const float4*)&W[k0 + k4];
                wS[gl][k4+0]=wv.x; wS[gl][k4+1]=wv.y; wS[gl][k4+2]=wv.z; wS[gl][k4+3]=wv.w;
            }
        }
        __syncthreads();
        #pragma unroll
        for (int kk = 0; kk < 32; kk++) {
            float xr[4];
            #pragma unroll
            for (int i = 0; i < 4; i++) xr[i] = xS[bx*4+i][kk];
            #pragma unroll
            for (int u = 0; u < 5; u++) {
                int o = ox + 32*u;
                float wr = (o < 2*OD) ? wS[o][kk] : 0.f;
                #pragma unroll
                for (int i = 0; i < 4; i++) acc[i][u] += xr[i]*wr;
            }
        }
        __syncthreads();
    }

    #pragma unroll
    for (int u = 0; u < 5; u++) {
        int o = ox + 32*u;
        if (o >= 2*OD) continue;
        int head = (o >= OD) ? 1 : 0;
        int oo = o - head*OD;
        float bterm = srcsel ? (head ? bins[oo] : bsub[oo]) : 0.f;
        #pragma unroll
        for (int i = 0; i < 4; i++) {
            int r = row0 + bx*4 + i;
            int iseq = r >> 8, b = r & 255;
            dst[((head*SXv + iseq)*OD + oo)*Bv + b] = acc[i][u] + bterm;
        }
    }
}

// ---------------- pair logsumexp + masked gathers -> output ----------------
__global__ __launch_bounds__(256) void pairs_kernel(float* __restrict__ out)
{
    const int i = blockIdx.x / SYv;
    const int j = blockIdx.x % SYv;
    const int b = threadIdx.x;

    const bool x_any = g_toks[i][b] >= 0;
    const bool y_any = g_tokt[j][b] >= 0;
    const bool valid = x_any && y_any && (j < SYv-1);
    const int tnext = (j+1 < SYv) ? g_tokt[j+1][b] : -1;
    const bool ins_ok = valid && (tnext != IND-1);

    const float* lx0 = &g_lx[0][i][0][0];
    const float* lx1 = &g_lx[1][i][0][0];
    const float* ly0 = &g_ly[0][j][0][0];
    const float* ly1 = &g_ly[1][j][0][0];

    float m0 = -1e30f, s0 = 0.f, m1 = -1e30f, s1 = 0.f;
    #pragma unroll 1
    for (int o = 0; o < OD; o++) {
        float z0 = lx0[o*Bv+b] + ly0[o*Bv+b];
        float nm0 = fmaxf(m0, z0);
        s0 = s0*__expf(m0-nm0) + __expf(z0-nm0);
        m0 = nm0;
        float z1 = lx1[o*Bv+b] + ly1[o*Bv+b];
        float nm1 = fmaxf(m1, z1);
        s1 = s1*__expf(m1-nm1) + __expf(z1-nm1);
        m1 = nm1;
    }
    const float lse0 = m0 + __logf(s0);   // sub head
    const float lse1 = m1 + __logf(s1);   // ins head

    float dlt  = valid ? (lx0[VV*Bv+b] + ly0[VV*Bv+b] - lse0) : BIG_NEG;
    float endv = valid ? (lx1[VV*Bv+b] + ly1[VV*Bv+b] - lse1) : BIG_NEG;
    float insv = BIG_NEG, subv = BIG_NEG;
    if (ins_ok) {
        if (tnext >= 0 && tnext < VV) {
            subv = lx0[tnext*Bv+b] + ly0[tnext*Bv+b] - lse0;
            insv = lx1[tnext*Bv+b] + ly1[tnext*Bv+b] - lse1;
        } else {
            insv = 0.f; subv = 0.f;
        }
    }

    const int base  = (i*SYv + j)*Bv + b;
    const int plane = SXv*SYv*Bv;
    out[0*plane + base] = insv;
    out[1*plane + base] = subv;
    out[2*plane + base] = endv;
    out[3*plane + base] = dlt;
}

// ---------------- launch ----------------
extern "C" void kernel_launch(void* const* d_in, const int* in_sizes, int n_in,
                              void* d_out, int out_size)
{
    const float* sources = (const float*)d_in[0];
    const float* targets = (const float*)d_in[1];
    const float* Wih_f = (const float*)d_in[2];
    const float* Whh_f = (const float*)d_in[3];
    const float* b_f   = (const float*)d_in[4];
    const float* Wih_r = (const float*)d_in[5];
    const float* Whh_r = (const float*)d_in[6];
    const float* b_r   = (const float*)d_in[7];
    const float* Wih_m = (const float*)d_in[8];
    const float* Whh_m = (const float*)d_in[9];
    const float* b_m   = (const float*)d_in[10];
    const float* W_sub = (const float*)d_in[11];
    const float* b_sub = (const float*)d_in[12];
    const float* W_ins = (const float*)d_in[13];
    const float* b_ins = (const float*)d_in[14];
    float* out = (float*)d_out;

    init_kernel<<<1024, 256>>>(sources, targets);
    for (int t = 0; t < SXv; t++) {
        lstm_step<<<128, 256>>>(t, Whh_f, Wih_f, b_f,
                                   Whh_r, Wih_r, b_r,
                                   Whh_m, Wih_m, b_m);
    }
    heads_kernel<<<dim3(272, 2), 256>>>(W_sub, b_sub, W_ins, b_ins);
    pairs_kernel<<<SXv*SYv, 256>>>(out);
}

// round 4
// speedup vs baseline: 6.5465x; 3.5968x over previous
#include <cuda_runtime.h>
#include <cuda_bf16.h>
#include <math.h>

#define Bv   256
#define SXv  34
#define SYv  34
#define H1   512
#define H2   1024
#define IND  66
#define OD   65
#define VV   64
#define BIG_NEG -1000000000.0f

// K-extended widths (HID + 66 onehot + 1 bias + pad to /32)
#define KEF  608            // 512 + 96
#define KEM  1120           // 1024 + 96
#define KEH  1056           // 1024 + 32 (bias col at 1024)
#define NF_  (16*128*KEF)
#define NM_  (32*128*KEM)
#define NH_  (144*KEH)

// ---------------- device scratch ----------------
__device__ __align__(256) __nv_bfloat16 g_WpF[NF_];
__device__ __align__(256) __nv_bfloat16 g_WpR[NF_];
__device__ __align__(256) __nv_bfloat16 g_WpM[NM_];
__device__ __align__(256) __nv_bfloat16 g_WpH[NH_];
__device__ __align__(256) __nv_bfloat16 g_xemb[SXv][Bv][2*H1];  // h fwd|rev, bf16
__device__ __align__(256) __nv_bfloat16 g_yemb[SYv][Bv][H2];
__device__ __align__(256) __nv_bfloat16 g_hzero[Bv][H2];
__device__ float g_cf[Bv][H1];
__device__ float g_cr[Bv][H1];
__device__ float g_cm[Bv][H2];
__device__ int   g_toks[SXv][Bv];
__device__ int   g_tokt[SYv][Bv];
__device__ float g_lx[2][SXv][OD][Bv];
__device__ float g_ly[2][SYv][OD][Bv];

__device__ __forceinline__ float sigm(float x){ return 1.0f/(1.0f+expf(-x)); }

#define LDM_X4(r0,r1,r2,r3,addr) \
    asm volatile("ldmatrix.sync.aligned.m8n8.x4.shared.b16 {%0,%1,%2,%3},[%4];" \
        : "=r"(r0),"=r"(r1),"=r"(r2),"=r"(r3) : "r"(addr))

#define MMA16816(d,a,b) \
    asm volatile("mma.sync.aligned.m16n8k16.row.col.f32.bf16.bf16.f32 " \
        "{%0,%1,%2,%3},{%4,%5,%6,%7},{%8,%9},{%0,%1,%2,%3};" \
        : "+f"(d[0]),"+f"(d[1]),"+f"(d[2]),"+f"(d[3]) \
        : "r"(a[0]),"r"(a[1]),"r"(a[2]),"r"(a[3]),"r"(b[0]),"r"(b[1]))

// ---------------- init: zero states + tokenize ----------------
__global__ void init_misc(const float* __restrict__ src, const float* __restrict__ tgt)
{
    int id = blockIdx.x * blockDim.x + threadIdx.x;   // 512x512 = 262144 threads
    if (id < Bv*H1) { ((float*)g_cf)[id] = 0.f; ((float*)g_cr)[id] = 0.f; }
    ((float*)g_cm)[id] = 0.f;
    ((__nv_bfloat16*)g_hzero)[id] = __float2bfloat16(0.f);
    if (id < SXv*Bv) {
        const float* p = src + (long)id * IND;
        int tok = -1;
        #pragma unroll 1
        for (int v = 0; v < IND; v++) if (p[v] > 0.5f) tok = v;
        ((int*)g_toks)[id] = tok;
        const float* q = tgt + (long)id * IND;
        tok = -1;
        #pragma unroll 1
        for (int v = 0; v < IND; v++) if (q[v] > 0.5f) tok = v;
        ((int*)g_tokt)[id] = tok;
    }
}

// ---------------- weight convert + permute to bf16 ----------------
// perm row lr: wm=lr>>6, mf=(lr>>4)&3, hi=(lr>>3)&1, x=lr&7
// gate q = mf, unit = tile*32 + wm*16 + hi*8 + x, global row = q*HID + unit
__global__ void convert_weights(
    const float* __restrict__ WihF, const float* __restrict__ WhhF, const float* __restrict__ bF,
    const float* __restrict__ WihR, const float* __restrict__ WhhR, const float* __restrict__ bR,
    const float* __restrict__ WihM, const float* __restrict__ WhhM, const float* __restrict__ bM,
    const float* __restrict__ Wsub, const float* __restrict__ bsub,
    const float* __restrict__ Wins, const float* __restrict__ bins)
{
    const long total = 2L*NF_ + NM_ + NH_;
    for (long id = (long)blockIdx.x*blockDim.x + threadIdx.x; id < total;
         id += (long)gridDim.x*blockDim.x) {
        long r = id;
        if (r < 2L*NF_) {
            int which = (r >= NF_);
            long q = r - (long)which*NF_;
            int tile = (int)(q / (128*KEF));
            int rem  = (int)(q % (128*KEF));
            int lr = rem / KEF, k = rem % KEF;
            int wm = lr>>6, mf = (lr>>4)&3, hi = (lr>>3)&1, x = lr&7;
            int grow = mf*H1 + tile*32 + wm*16 + hi*8 + x;
            const float* Whh = which ? WhhR : WhhF;
            const float* Wih = which ? WihR : WihF;
            const float* bb  = which ? bR   : bF;
            float v;
            if (k < H1) v = Whh[(long)grow*H1 + k];
            else { int c = k - H1; v = (c < IND) ? Wih[grow*IND + c] : (c == IND ? bb[grow] : 0.f); }
            (which ? g_WpR : g_WpF)[q] = __float2bfloat16(v);
        } else if ((r -= 2L*NF_) < NM_) {
            int tile = (int)(r / (128*KEM));
            int rem  = (int)(r % (128*KEM));
            int lr = rem / KEM, k = rem % KEM;
            int wm = lr>>6, mf = (lr>>4)&3, hi = (lr>>3)&1, x = lr&7;
            int grow = mf*H2 + tile*32 + wm*16 + hi*8 + x;
            float v;
            if (k < H2) v = WhhM[(long)grow*H2 + k];
            else { int c = k - H2; v = (c < IND) ? WihM[grow*IND + c] : (c == IND ? bM[grow] : 0.f); }
            g_WpM[r] = __float2bfloat16(v);
        } else {
            r -= NM_;
            int o = (int)(r / KEH), k = (int)(r % KEH);
            float v = 0.f;
            if (o < OD)           v = (k < H2) ? Wsub[(long)o*H2 + k]      : (k == H2 ? bsub[o]    : 0.f);
            else if (o < 2*OD)    v = (k < H2) ? Wins[(long)(o-OD)*H2 + k] : (k == H2 ? bins[o-OD] : 0.f);
            g_WpH[r] = __float2bfloat16(v);
        }
    }
}

// ---------------- fused 3-LSTM step via mma.sync bf16 ----------------
// 128 blocks: [0,32) fwd, [32,64) rev, [64,128) modern. Tile 128 rows x 128 batch.
__global__ __launch_bounds__(256) void lstm_step_mma(int t)
{
    __shared__ __nv_bfloat16 As[2][128][40];
    __shared__ __nv_bfloat16 Bs[2][128][40];
    __shared__ int tokS[128];

    const int tid = threadIdx.x;
    int blk = blockIdx.x;

    const __nv_bfloat16 *Wp, *Bsrc;
    __nv_bfloat16 *embout;
    float *cbuf;
    const int *tokp;
    int HIDk, KE, nreg, h0, boff, ooff, b0g;

    if (blk < 32) {
        int tile = blk >> 1, bh = blk & 1;
        Wp = g_WpF + (size_t)tile*128*KEF; KE = KEF; HIDk = H1; nreg = 16;
        h0 = tile*32; b0g = bh*128;
        Bsrc = (t == 0) ? &g_hzero[0][0] : &g_xemb[t-1][0][0]; boff = 0;
        tokp = &g_toks[t][0]; cbuf = &g_cf[0][0];
        embout = &g_xemb[t][0][0]; ooff = 0;
    } else if (blk < 64) {
        int tile = (blk-32) >> 1, bh = (blk-32) & 1;
        Wp = g_WpR + (size_t)tile*128*KEF; KE = KEF; HIDk = H1; nreg = 16;
        h0 = tile*32; b0g = bh*128;
        Bsrc = (t == 0) ? &g_hzero[0][0] : &g_xemb[SXv-t][0][0]; boff = H1;
        tokp = &g_toks[SXv-1-t][0]; cbuf = &g_cr[0][0];
        embout = &g_xemb[SXv-1-t][0][0]; ooff = H1;
    } else {
        int tile = (blk-64) >> 1, bh = (blk-64) & 1;
        Wp = g_WpM + (size_t)tile*128*KEM; KE = KEM; HIDk = H2; nreg = 32;
        h0 = tile*32; b0g = bh*128;
        Bsrc = (t == 0) ? &g_hzero[0][0] : &g_yemb[t-1][0][0]; boff = 0;
        tokp = &g_tokt[t][0]; cbuf = &g_cm[0][0];
        embout = &g_yemb[t][0][0]; ooff = 0;
    }
    const int nch = nreg + 3;

    if (tid < 128) tokS[tid] = tokp[b0g + tid];
    __syncthreads();

    const int lane = tid & 31, warp = tid >> 5;
    const int wm = warp >> 2, wn = warp & 3;

    float acc[4][4][4];
    #pragma unroll
    for (int a = 0; a < 4; a++)
        #pragma unroll
        for (int b = 0; b < 4; b++)
            #pragma unroll
            for (int c = 0; c < 4; c++) acc[a][b][c] = 0.f;

    // stage chunk 0
    {
        #pragma unroll
        for (int s = 0; s < 2; s++) {
            int u = tid*2 + s, row = u >> 2, kq = u & 3;
            *(uint4*)&As[0][row][kq*8] = *(const uint4*)(Wp + (size_t)row*KE + kq*8);
            *(uint4*)&Bs[0][row][kq*8] = *(const uint4*)(Bsrc + (size_t)(b0g+row)*1024 + boff + kq*8);
        }
    }

    for (int ch = 0; ch < nch; ch++) {
        const int p = ch & 1;
        __syncthreads();
        // stage next chunk into alt buffer
        if (ch + 1 < nch) {
            const int cn = ch + 1, pa = p ^ 1;
            #pragma unroll
            for (int s = 0; s < 2; s++) {
                int u = tid*2 + s, row = u >> 2, kq = u & 3;
                *(uint4*)&As[pa][row][kq*8] = *(const uint4*)(Wp + (size_t)row*KE + cn*32 + kq*8);
            }
            if (cn < nreg) {
                #pragma unroll
                for (int s = 0; s < 2; s++) {
                    int u = tid*2 + s, row = u >> 2, kq = u & 3;
                    *(uint4*)&Bs[pa][row][kq*8] =
                        *(const uint4*)(Bsrc + (size_t)(b0g+row)*1024 + boff + cn*32 + kq*8);
                }
            } else {
                int kbase = (cn - nreg) * 32;
                #pragma unroll
                for (int s = 0; s < 16; s++) {
                    int idx = tid + s*256;
                    int n = idx >> 5, kk = idx & 31;
                    int v = kbase + kk;
                    float val = (v == tokS[n] || v == IND) ? 1.f : 0.f;
                    Bs[pa][n][kk] = __float2bfloat16(val);
                }
            }
        }
        // compute chunk p
        const unsigned asb = (unsigned)__cvta_generic_to_shared(&As[p][0][0]);
        #pragma unroll
        for (int h16 = 0; h16 < 2; h16++) {
            unsigned a[4][4];
            #pragma unroll
            for (int mf = 0; mf < 4; mf++) {
                unsigned addr = asb + (((wm*64 + mf*16 + (lane & 15))*40
                                + h16*16 + ((lane >> 4) << 3)) << 1);
                LDM_X4(a[mf][0], a[mf][1], a[mf][2], a[mf][3], addr);
            }
            unsigned b[4][2];
            #pragma unroll
            for (int nf = 0; nf < 4; nf++) {
                const __nv_bfloat16* bp = &Bs[p][wn*32 + nf*8 + (lane >> 2)][h16*16 + 2*(lane & 3)];
                b[nf][0] = *(const unsigned*)bp;
                b[nf][1] = *(const unsigned*)(bp + 8);
            }
            #pragma unroll
            for (int mf = 0; mf < 4; mf++)
                #pragma unroll
                for (int nf = 0; nf < 4; nf++)
                    MMA16816(acc[mf][nf], a[mf], b[nf]);
        }
    }

    // epilogue: in-register LSTM cell update (q = mf, unit = h0+wm*16+hi*8+x)
    const int x = lane >> 2, cp = lane & 3;
    #pragma unroll
    for (int hi = 0; hi < 2; hi++) {
        const int unit = h0 + wm*16 + hi*8 + x;
        #pragma unroll
        for (int nf = 0; nf < 4; nf++) {
            #pragma unroll
            for (int cc = 0; cc < 2; cc++) {
                const int b = b0g + wn*32 + nf*8 + 2*cp + cc;
                const int e = hi*2 + cc;
                float gi = acc[0][nf][e], gf = acc[1][nf][e];
                float gg = acc[2][nf][e], go = acc[3][nf][e];
                float cold = cbuf[(size_t)b*HIDk + unit];
                float cn = sigm(gf)*cold + sigm(gi)*tanhf(gg);
                float hn = sigm(go)*tanhf(cn);
                cbuf[(size_t)b*HIDk + unit] = cn;
                embout[(size_t)b*1024 + ooff + unit] = __float2bfloat16(hn);
            }
        }
    }
}

// ---------------- heads via mma.sync bf16 ----------------
// grid (34, src, bhalf), 288 threads = 9 warps, warp w: rows [w*16, w*16+16) x 128 batch
__global__ __launch_bounds__(288) void heads_mma()
{
    __shared__ __nv_bfloat16 As[2][144][40];
    __shared__ __nv_bfloat16 Bs[2][128][40];

    const int i = blockIdx.x, ss = blockIdx.y, bh = blockIdx.z;
    const int tid = threadIdx.x;
    const __nv_bfloat16* Bsrc = ss ? &g_yemb[i][0][0] : &g_xemb[i][0][0];
    const int b0g = bh * 128;
    const int nch = 32 + ss;      // ly gets the bias ext chunk

    const int lane = tid & 31, w = tid >> 5;

    float acc[16][4];
    #pragma unroll
    for (int nf = 0; nf < 16; nf++)
        #pragma unroll
        for (int c = 0; c < 4; c++) acc[nf][c] = 0.f;

    // stage chunk 0
    {
        #pragma unroll
        for (int s = 0; s < 2; s++) {
            int u = tid*2 + s, row = u >> 2, kq = u & 3;   // 576 units = 144 rows x 4
            *(uint4*)&As[0][row][kq*8] = *(const uint4*)(g_WpH + (size_t)row*KEH + kq*8);
        }
        #pragma unroll
        for (int s = 0; s < 2; s++) {
            int u = tid + s*288;
            if (u < 512) {
                int row = u >> 2, kq = u & 3;
                *(uint4*)&Bs[0][row][kq*8] = *(const uint4*)(Bsrc + (size_t)(b0g+row)*1024 + kq*8);
            }
        }
    }

    for (int ch = 0; ch < nch; ch++) {
        const int p = ch & 1;
        __syncthreads();
        if (ch + 1 < nch) {
            const int cn = ch + 1, pa = p ^ 1;
            #pragma unroll
            for (int s = 0; s < 2; s++) {
                int u = tid*2 + s, row = u >> 2, kq = u & 3;
                *(uint4*)&As[pa][row][kq*8] = *(const uint4*)(g_WpH + (size_t)row*KEH + cn*32 + kq*8);
            }
            if (cn < 32) {
                #pragma unroll
                for (int s = 0; s < 2; s++) {
                    int u = tid + s*288;
                    if (u < 512) {
                        int row = u >> 2, kq = u & 3;
                        *(uint4*)&Bs[pa][row][kq*8] =
                            *(const uint4*)(Bsrc + (size_t)(b0g+row)*1024 + cn*32 + kq*8);
                    }
                }
            } else {
                #pragma unroll
                for (int s = 0; s < 15; s++) {
                    int idx = tid + s*288;
                    if (idx < 4096) {
                        int n = idx >> 5, kk = idx & 31;
                        Bs[pa][n][kk] = __float2bfloat16(kk == 0 ? 1.f : 0.f);
                    }
                }
            }
        }
        const unsigned asb = (unsigned)__cvta_generic_to_shared(&As[p][0][0]);
        #pragma unroll
        for (int h16 = 0; h16 < 2; h16++) {
            unsigned a[4];
            unsigned addr = asb + (((w*16 + (lane & 15))*40 + h16*16 + ((lane >> 4) << 3)) << 1);
            LDM_X4(a[0], a[1], a[2], a[3], addr);
            #pragma unroll
            for (int nf = 0; nf < 16; nf++) {
                unsigned b[2];
                const __nv_bfloat16* bp = &Bs[p][nf*8 + (lane >> 2)][h16*16 + 2*(lane & 3)];
                b[0] = *(const unsigned*)bp;
                b[1] = *(const unsigned*)(bp + 8);
                MMA16816(acc[nf], a, b);
            }
        }
    }

    // epilogue
    const int x = lane >> 2, cp = lane & 3;
    #pragma unroll
    for (int hi = 0; hi < 2; hi++) {
        const int op = w*16 + hi*8 + x;
        if (op < 2*OD) {
            const int head = (op >= OD);
            const int oo = op - head*OD;
            float* dst = ss ? &g_ly[head][i][oo][0] : &g_lx[head][i][oo][0];
            #pragma unroll
            for (int nf = 0; nf < 16; nf++) {
                #pragma unroll
                for (int cc = 0; cc < 2; cc++) {
                    const int b = b0g + nf*8 + 2*cp + cc;
                    dst[b] = acc[nf][hi*2 + cc];
                }
            }
        }
    }
}

// ---------------- pair logsumexp + masked gathers -> output ----------------
__global__ __launch_bounds__(256) void pairs_kernel(float* __restrict__ out)
{
    const int i = blockIdx.x / SYv;
    const int j = blockIdx.x % SYv;
    const int b = threadIdx.x;

    const bool x_any = g_toks[i][b] >= 0;
    const bool y_any = g_tokt[j][b] >= 0;
    const bool valid = x_any && y_any && (j < SYv-1);
    const int tnext = (j+1 < SYv) ? g_tokt[j+1][b] : -1;
    const bool ins_ok = valid && (tnext != IND-1);

    const float* lx0 = &g_lx[0][i][0][0];
    const float* lx1 = &g_lx[1][i][0][0];
    const float* ly0 = &g_ly[0][j][0][0];
    const float* ly1 = &g_ly[1][j][0][0];

    float m0 = -1e30f, s0 = 0.f, m1 = -1e30f, s1 = 0.f;
    #pragma unroll 1
    for (int o = 0; o < OD; o++) {
        float z0 = lx0[o*Bv+b] + ly0[o*Bv+b];
        float nm0 = fmaxf(m0, z0);
        s0 = s0*__expf(m0-nm0) + __expf(z0-nm0);
        m0 = nm0;
        float z1 = lx1[o*Bv+b] + ly1[o*Bv+b];
        float nm1 = fmaxf(m1, z1);
        s1 = s1*__expf(m1-nm1) + __expf(z1-nm1);
        m1 = nm1;
    }
    const float lse0 = m0 + __logf(s0);
    const float lse1 = m1 + __logf(s1);

    float dlt  = valid ? (lx0[VV*Bv+b] + ly0[VV*Bv+b] - lse0) : BIG_NEG;
    float endv = valid ? (lx1[VV*Bv+b] + ly1[VV*Bv+b] - lse1) : BIG_NEG;
    float insv = BIG_NEG, subv = BIG_NEG;
    if (ins_ok) {
        if (tnext >= 0 && tnext < VV) {
            subv = lx0[tnext*Bv+b] + ly0[tnext*Bv+b] - lse0;
            insv = lx1[tnext*Bv+b] + ly1[tnext*Bv+b] - lse1;
        } else {
            insv = 0.f; subv = 0.f;
        }
    }

    const int base  = (i*SYv + j)*Bv + b;
    const int plane = SXv*SYv*Bv;
    out[0*plane + base] = insv;
    out[1*plane + base] = subv;
    out[2*plane + base] = endv;
    out[3*plane + base] = dlt;
}

// ---------------- launch ----------------
extern "C" void kernel_launch(void* const* d_in, const int* in_sizes, int n_in,
                              void* d_out, int out_size)
{
    const float* sources = (const float*)d_in[0];
    const float* targets = (const float*)d_in[1];
    const float* Wih_f = (const float*)d_in[2];
    const float* Whh_f = (const float*)d_in[3];
    const float* b_f   = (const float*)d_in[4];
    const float* Wih_r = (const float*)d_in[5];
    const float* Whh_r = (const float*)d_in[6];
    const float* b_r   = (const float*)d_in[7];
    const float* Wih_m = (const float*)d_in[8];
    const float* Whh_m = (const float*)d_in[9];
    const float* b_m   = (const float*)d_in[10];
    const float* W_sub = (const float*)d_in[11];
    const float* b_sub = (const float*)d_in[12];
    const float* W_ins = (const float*)d_in[13];
    const float* b_ins = (const float*)d_in[14];
    float* out = (float*)d_out;

    init_misc<<<512, 512>>>(sources, targets);
    convert_weights<<<2048, 512>>>(Wih_f, Whh_f, b_f, Wih_r, Whh_r, b_r,
                                   Wih_m, Whh_m, b_m, W_sub, b_sub, W_ins, b_ins);
    for (int t = 0; t < SXv; t++)
        lstm_step_mma<<<128, 256>>>(t);
    heads_mma<<<dim3(SXv, 2, 2), 288>>>();
    pairs_kernel<<<SXv*SYv, 256>>>(out);
}

// round 5
// speedup vs baseline: 9.0519x; 1.3827x over previous
#include <cuda_runtime.h>
#include <cuda_bf16.h>
#include <math.h>

#define Bv   256
#define SXv  34
#define SYv  34
#define H1   512
#define H2   1024
#define IND  66
#define OD   65
#define VV   64
#define BIG_NEG -1000000000.0f

// K-extended widths (HID + 66 onehot + 1 bias + pad to /32)
#define KEF  608
#define KEM  1120
#define KEH  1056
#define NF_  (16*128*KEF)
#define NM_  (32*128*KEM)
#define NH_  (144*KEH)
#define STG  4

// ---------------- device scratch ----------------
__device__ __align__(256) __nv_bfloat16 g_WpF[NF_];
__device__ __align__(256) __nv_bfloat16 g_WpR[NF_];
__device__ __align__(256) __nv_bfloat16 g_WpM[NM_];
__device__ __align__(256) __nv_bfloat16 g_WpH[NH_];
__device__ __align__(256) __nv_bfloat16 g_xemb[SXv][Bv][2*H1];
__device__ __align__(256) __nv_bfloat16 g_yemb[SYv][Bv][H2];
__device__ __align__(256) __nv_bfloat16 g_hzero[Bv][H2];
__device__ float g_cf[Bv][H1];
__device__ float g_cr[Bv][H1];
__device__ float g_cm[Bv][H2];
__device__ int   g_toks[SXv][Bv];
__device__ int   g_tokt[SYv][Bv];
__device__ float g_lx[2][SXv][OD][Bv];
__device__ float g_ly[2][SYv][OD][Bv];

__device__ __forceinline__ float sigm(float x){ return 1.0f/(1.0f+expf(-x)); }

#define LDM_X4(r0,r1,r2,r3,addr) \
    asm volatile("ldmatrix.sync.aligned.m8n8.x4.shared.b16 {%0,%1,%2,%3},[%4];" \
        : "=r"(r0),"=r"(r1),"=r"(r2),"=r"(r3) : "r"(addr))

#define MMA16816(d,a,b) \
    asm volatile("mma.sync.aligned.m16n8k16.row.col.f32.bf16.bf16.f32 " \
        "{%0,%1,%2,%3},{%4,%5,%6,%7},{%8,%9},{%0,%1,%2,%3};" \
        : "+f"(d[0]),"+f"(d[1]),"+f"(d[2]),"+f"(d[3]) \
        : "r"(a[0]),"r"(a[1]),"r"(a[2]),"r"(a[3]),"r"(b[0]),"r"(b[1]))

#define CP16(dst,src) \
    asm volatile("cp.async.cg.shared.global [%0],[%1],16;" :: "r"(dst),"l"(src))
#define CP_COMMIT() asm volatile("cp.async.commit_group;" ::: "memory")

// ---------------- init ----------------
__global__ void init_misc(const float* __restrict__ src, const float* __restrict__ tgt)
{
    int id = blockIdx.x * blockDim.x + threadIdx.x;
    if (id < Bv*H1) { ((float*)g_cf)[id] = 0.f; ((float*)g_cr)[id] = 0.f; }
    ((float*)g_cm)[id] = 0.f;
    ((__nv_bfloat16*)g_hzero)[id] = __float2bfloat16(0.f);
    if (id < SXv*Bv) {
        const float* p = src + (long)id * IND;
        int tok = -1;
        #pragma unroll 1
        for (int v = 0; v < IND; v++) if (p[v] > 0.5f) tok = v;
        ((int*)g_toks)[id] = tok;
        const float* q = tgt + (long)id * IND;
        tok = -1;
        #pragma unroll 1
        for (int v = 0; v < IND; v++) if (q[v] > 0.5f) tok = v;
        ((int*)g_tokt)[id] = tok;
    }
}

// ---------------- weight convert + permute to bf16 ----------------
// new perm for 16-warp layout: lr = wm*32 + mf*16 + hi*8 + x
// gate q = mf*2+hi, unit = tile*32 + wm*8 + x, global row = q*HID + unit
__global__ void convert_weights(
    const float* __restrict__ WihF, const float* __restrict__ WhhF, const float* __restrict__ bF,
    const float* __restrict__ WihR, const float* __restrict__ WhhR, const float* __restrict__ bR,
    const float* __restrict__ WihM, const float* __restrict__ WhhM, const float* __restrict__ bM,
    const float* __restrict__ Wsub, const float* __restrict__ bsub,
    const float* __restrict__ Wins, const float* __restrict__ bins)
{
    const long total = 2L*NF_ + NM_ + NH_;
    for (long id = (long)blockIdx.x*blockDim.x + threadIdx.x; id < total;
         id += (long)gridDim.x*blockDim.x) {
        long r = id;
        if (r < 2L*NF_) {
            int which = (r >= NF_);
            long q = r - (long)which*NF_;
            int tile = (int)(q / (128*KEF));
            int rem  = (int)(q % (128*KEF));
            int lr = rem / KEF, k = rem % KEF;
            int wm = lr>>5, mf = (lr>>4)&1, hi = (lr>>3)&1, x = lr&7;
            int grow = (mf*2+hi)*H1 + tile*32 + wm*8 + x;
            const float* Whh = which ? WhhR : WhhF;
            const float* Wih = which ? WihR : WihF;
            const float* bb  = which ? bR   : bF;
            float v;
            if (k < H1) v = Whh[(long)grow*H1 + k];
            else { int c = k - H1; v = (c < IND) ? Wih[grow*IND + c] : (c == IND ? bb[grow] : 0.f); }
            (which ? g_WpR : g_WpF)[q] = __float2bfloat16(v);
        } else if ((r -= 2L*NF_) < NM_) {
            int tile = (int)(r / (128*KEM));
            int rem  = (int)(r % (128*KEM));
            int lr = rem / KEM, k = rem % KEM;
            int wm = lr>>5, mf = (lr>>4)&1, hi = (lr>>3)&1, x = lr&7;
            int grow = (mf*2+hi)*H2 + tile*32 + wm*8 + x;
            float v;
            if (k < H2) v = WhhM[(long)grow*H2 + k];
            else { int c = k - H2; v = (c < IND) ? WihM[grow*IND + c] : (c == IND ? bM[grow] : 0.f); }
            g_WpM[r] = __float2bfloat16(v);
        } else {
            r -= NM_;
            int o = (int)(r / KEH), k = (int)(r % KEH);
            float v = 0.f;
            if (o < OD)           v = (k < H2) ? Wsub[(long)o*H2 + k]      : (k == H2 ? bsub[o]    : 0.f);
            else if (o < 2*OD)    v = (k < H2) ? Wins[(long)(o-OD)*H2 + k] : (k == H2 ? bins[o-OD] : 0.f);
            g_WpH[r] = __float2bfloat16(v);
        }
    }
}

// ---------------- fused 3-LSTM step: 512 threads, cp.async 4-stage pipeline ----
// 128 blocks: [0,32) fwd, [32,64) rev, [64,128) modern. Tile 128 rows x 128 batch.
__global__ __launch_bounds__(512) void lstm_step_mma(int t)
{
    extern __shared__ __nv_bfloat16 dynS[];          // As[STG][128][40] | Bs[STG][128][40]
    __nv_bfloat16 (*As)[128][40] = (__nv_bfloat16 (*)[128][40])dynS;
    __nv_bfloat16 (*Bs)[128][40] = (__nv_bfloat16 (*)[128][40])(dynS + STG*128*40);
    __shared__ int tokS[128];

    const int tid = threadIdx.x;
    int blk = blockIdx.x;

    const __nv_bfloat16 *Wp, *Bsrc;
    __nv_bfloat16 *embout;
    float *cbuf;
    const int *tokp;
    int HIDk, KE, nreg, h0, boff, ooff, b0g;

    if (blk < 32) {
        int tile = blk >> 1, bh = blk & 1;
        Wp = g_WpF + (size_t)tile*128*KEF; KE = KEF; HIDk = H1; nreg = 16;
        h0 = tile*32; b0g = bh*128;
        Bsrc = (t == 0) ? &g_hzero[0][0] : &g_xemb[t-1][0][0]; boff = 0;
        tokp = &g_toks[t][0]; cbuf = &g_cf[0][0];
        embout = &g_xemb[t][0][0]; ooff = 0;
    } else if (blk < 64) {
        int tile = (blk-32) >> 1, bh = (blk-32) & 1;
        Wp = g_WpR + (size_t)tile*128*KEF; KE = KEF; HIDk = H1; nreg = 16;
        h0 = tile*32; b0g = bh*128;
        Bsrc = (t == 0) ? &g_hzero[0][0] : &g_xemb[SXv-t][0][0]; boff = H1;
        tokp = &g_toks[SXv-1-t][0]; cbuf = &g_cr[0][0];
        embout = &g_xemb[SXv-1-t][0][0]; ooff = H1;
    } else {
        int tile = (blk-64) >> 1, bh = (blk-64) & 1;
        Wp = g_WpM + (size_t)tile*128*KEM; KE = KEM; HIDk = H2; nreg = 32;
        h0 = tile*32; b0g = bh*128;
        Bsrc = (t == 0) ? &g_hzero[0][0] : &g_yemb[t-1][0][0]; boff = 0;
        tokp = &g_tokt[t][0]; cbuf = &g_cm[0][0];
        embout = &g_yemb[t][0][0]; ooff = 0;
    }
    const int nch = nreg + 3;

    if (tid < 128) tokS[tid] = tokp[b0g + tid];
    __syncthreads();

    const int lane = tid & 31, warp = tid >> 5;
    const int wm = warp >> 2, wn = warp & 3;

    const unsigned As_u = (unsigned)__cvta_generic_to_shared(&As[0][0][0]);
    const unsigned Bs_u = (unsigned)__cvta_generic_to_shared(&Bs[0][0][0]);
    const __nv_bfloat16 bfone = __float2bfloat16(1.f);
    const __nv_bfloat16 bfzero = __float2bfloat16(0.f);

    // stage chunk ci into slot s (one commit group per call)
    #define STAGE(ci, s) do {                                                       \
        int row_ = tid >> 2, kq_ = tid & 3;                                         \
        unsigned da_ = As_u + (unsigned)((((s)*128 + row_)*40 + kq_*8) << 1);       \
        CP16(da_, Wp + (size_t)row_*KE + (ci)*32 + kq_*8);                          \
        if ((ci) < nreg) {                                                          \
            unsigned db_ = Bs_u + (unsigned)((((s)*128 + row_)*40 + kq_*8) << 1);   \
            CP16(db_, Bsrc + (size_t)(b0g+row_)*1024 + boff + (ci)*32 + kq_*8);     \
        } else {                                                                    \
            int kbase_ = ((ci) - nreg) * 32;                                        \
            _Pragma("unroll")                                                       \
            for (int s2_ = 0; s2_ < 8; s2_++) {                                     \
                int idx_ = tid + s2_*512;                                           \
                int n_ = idx_ >> 5, kk_ = idx_ & 31;                                \
                int v_ = kbase_ + kk_;                                              \
                Bs[s][n_][kk_] = (v_ == tokS[n_] || v_ == IND) ? bfone : bfzero;    \
            }                                                                       \
        }                                                                           \
        CP_COMMIT();                                                                \
    } while (0)

    float acc[2][4][4];
    #pragma unroll
    for (int a = 0; a < 2; a++)
        #pragma unroll
        for (int b = 0; b < 4; b++)
            #pragma unroll
            for (int c = 0; c < 4; c++) acc[a][b][c] = 0.f;

    STAGE(0, 0); STAGE(1, 1); STAGE(2, 2);

    for (int ch = 0; ch < nch; ch++) {
        if (ch <= nch - 3)       asm volatile("cp.async.wait_group 2;" ::: "memory");
        else if (ch == nch - 2)  asm volatile("cp.async.wait_group 1;" ::: "memory");
        else                     asm volatile("cp.async.wait_group 0;" ::: "memory");
        __syncthreads();
        if (ch + 3 < nch) { int cn = ch + 3; STAGE(cn, cn & (STG-1)); }

        const int p = ch & (STG-1);
        const unsigned asb = As_u + (unsigned)((p*128*40) << 1);
        #pragma unroll
        for (int h16 = 0; h16 < 2; h16++) {
            unsigned a[2][4];
            #pragma unroll
            for (int mf = 0; mf < 2; mf++) {
                unsigned addr = asb + (unsigned)((((wm*32 + mf*16 + (lane & 15))*40)
                                + h16*16 + ((lane >> 4) << 3)) << 1);
                LDM_X4(a[mf][0], a[mf][1], a[mf][2], a[mf][3], addr);
            }
            unsigned b[4][2];
            #pragma unroll
            for (int nf = 0; nf < 4; nf++) {
                const __nv_bfloat16* bp = &Bs[p][wn*32 + nf*8 + (lane >> 2)][h16*16 + 2*(lane & 3)];
                b[nf][0] = *(const unsigned*)bp;
                b[nf][1] = *(const unsigned*)(bp + 8);
            }
            #pragma unroll
            for (int mf = 0; mf < 2; mf++)
                #pragma unroll
                for (int nf = 0; nf < 4; nf++)
                    MMA16816(acc[mf][nf], a[mf], b[nf]);
        }
    }

    // epilogue: all 4 gates of unit (h0 + wm*8 + lane>>2) are in-thread
    // q = mf*2 + hi: acc[mf][nf][cc] (hi=0), acc[mf][nf][2+cc] (hi=1)
    const int x4 = lane >> 2, tig = lane & 3;
    const int unit = h0 + wm*8 + x4;
    #pragma unroll
    for (int nf = 0; nf < 4; nf++) {
        #pragma unroll
        for (int cc = 0; cc < 2; cc++) {
            const int b = b0g + wn*32 + nf*8 + 2*tig + cc;
            float gi = acc[0][nf][cc];
            float gf = acc[0][nf][2+cc];
            float gg = acc[1][nf][cc];
            float go = acc[1][nf][2+cc];
            float cold = cbuf[(size_t)b*HIDk + unit];
            float cn = sigm(gf)*cold + sigm(gi)*tanhf(gg);
            float hn = sigm(go)*tanhf(cn);
            cbuf[(size_t)b*HIDk + unit] = cn;
            embout[(size_t)b*1024 + ooff + unit] = __float2bfloat16(hn);
        }
    }
    #undef STAGE
}

// ---------------- heads via mma.sync bf16 ----------------
__global__ __launch_bounds__(288) void heads_mma()
{
    __shared__ __nv_bfloat16 As[2][144][40];
    __shared__ __nv_bfloat16 Bs[2][128][40];

    const int i = blockIdx.x, ss = blockIdx.y, bh = blockIdx.z;
    const int tid = threadIdx.x;
    const __nv_bfloat16* Bsrc = ss ? &g_yemb[i][0][0] : &g_xemb[i][0][0];
    const int b0g = bh * 128;
    const int nch = 32 + ss;

    const int lane = tid & 31, w = tid >> 5;

    float acc[16][4];
    #pragma unroll
    for (int nf = 0; nf < 16; nf++)
        #pragma unroll
        for (int c = 0; c < 4; c++) acc[nf][c] = 0.f;

    {
        #pragma unroll
        for (int s = 0; s < 2; s++) {
            int u = tid*2 + s, row = u >> 2, kq = u & 3;
            *(uint4*)&As[0][row][kq*8] = *(const uint4*)(g_WpH + (size_t)row*KEH + kq*8);
        }
        #pragma unroll
        for (int s = 0; s < 2; s++) {
            int u = tid + s*288;
            if (u < 512) {
                int row = u >> 2, kq = u & 3;
                *(uint4*)&Bs[0][row][kq*8] = *(const uint4*)(Bsrc + (size_t)(b0g+row)*1024 + kq*8);
            }
        }
    }

    for (int ch = 0; ch < nch; ch++) {
        const int p = ch & 1;
        __syncthreads();
        if (ch + 1 < nch) {
            const int cn = ch + 1, pa = p ^ 1;
            #pragma unroll
            for (int s = 0; s < 2; s++) {
                int u = tid*2 + s, row = u >> 2, kq = u & 3;
                *(uint4*)&As[pa][row][kq*8] = *(const uint4*)(g_WpH + (size_t)row*KEH + cn*32 + kq*8);
            }
            if (cn < 32) {
                #pragma unroll
                for (int s = 0; s < 2; s++) {
                    int u = tid + s*288;
                    if (u < 512) {
                        int row = u >> 2, kq = u & 3;
                        *(uint4*)&Bs[pa][row][kq*8] =
                            *(const uint4*)(Bsrc + (size_t)(b0g+row)*1024 + cn*32 + kq*8);
                    }
                }
            } else {
                #pragma unroll
                for (int s = 0; s < 15; s++) {
                    int idx = tid + s*288;
                    if (idx < 4096) {
                        int n = idx >> 5, kk = idx & 31;
                        Bs[pa][n][kk] = __float2bfloat16(kk == 0 ? 1.f : 0.f);
                    }
                }
            }
        }
        const unsigned asb = (unsigned)__cvta_generic_to_shared(&As[p][0][0]);
        #pragma unroll
        for (int h16 = 0; h16 < 2; h16++) {
            unsigned a[4];
            unsigned addr = asb + (((w*16 + (lane & 15))*40 + h16*16 + ((lane >> 4) << 3)) << 1);
            LDM_X4(a[0], a[1], a[2], a[3], addr);
            #pragma unroll
            for (int nf = 0; nf < 16; nf++) {
                unsigned b[2];
                const __nv_bfloat16* bp = &Bs[p][nf*8 + (lane >> 2)][h16*16 + 2*(lane & 3)];
                b[0] = *(const unsigned*)bp;
                b[1] = *(const unsigned*)(bp + 8);
                MMA16816(acc[nf], a, b);
            }
        }
    }

    const int x = lane >> 2, cp = lane & 3;
    #pragma unroll
    for (int hi = 0; hi < 2; hi++) {
        const int op = w*16 + hi*8 + x;
        if (op < 2*OD) {
            const int head = (op >= OD);
            const int oo = op - head*OD;
            float* dst = ss ? &g_ly[head][i][oo][0] : &g_lx[head][i][oo][0];
            #pragma unroll
            for (int nf = 0; nf < 16; nf++) {
                #pragma unroll
                for (int cc = 0; cc < 2; cc++) {
                    const int b = b0g + nf*8 + 2*cp + cc;
                    dst[b] = acc[nf][hi*2 + cc];
                }
            }
        }
    }
}

// ---------------- pair logsumexp + masked gathers -> output ----------------
__global__ __launch_bounds__(256) void pairs_kernel(float* __restrict__ out)
{
    const int i = blockIdx.x / SYv;
    const int j = blockIdx.x % SYv;
    const int b = threadIdx.x;

    const bool x_any = g_toks[i][b] >= 0;
    const bool y_any = g_tokt[j][b] >= 0;
    const bool valid = x_any && y_any && (j < SYv-1);
    const int tnext = (j+1 < SYv) ? g_tokt[j+1][b] : -1;
    const bool ins_ok = valid && (tnext != IND-1);

    const float* lx0 = &g_lx[0][i][0][0];
    const float* lx1 = &g_lx[1][i][0][0];
    const float* ly0 = &g_ly[0][j][0][0];
    const float* ly1 = &g_ly[1][j][0][0];

    float m0 = -1e30f, s0 = 0.f, m1 = -1e30f, s1 = 0.f;
    #pragma unroll 1
    for (int o = 0; o < OD; o++) {
        float z0 = lx0[o*Bv+b] + ly0[o*Bv+b];
        float nm0 = fmaxf(m0, z0);
        s0 = s0*__expf(m0-nm0) + __expf(z0-nm0);
        m0 = nm0;
        float z1 = lx1[o*Bv+b] + ly1[o*Bv+b];
        float nm1 = fmaxf(m1, z1);
        s1 = s1*__expf(m1-nm1) + __expf(z1-nm1);
        m1 = nm1;
    }
    const float lse0 = m0 + __logf(s0);
    const float lse1 = m1 + __logf(s1);

    float dlt  = valid ? (lx0[VV*Bv+b] + ly0[VV*Bv+b] - lse0) : BIG_NEG;
    float endv = valid ? (lx1[VV*Bv+b] + ly1[VV*Bv+b] - lse1) : BIG_NEG;
    float insv = BIG_NEG, subv = BIG_NEG;
    if (ins_ok) {
        if (tnext >= 0 && tnext < VV) {
            subv = lx0[tnext*Bv+b] + ly0[tnext*Bv+b] - lse0;
            insv = lx1[tnext*Bv+b] + ly1[tnext*Bv+b] - lse1;
        } else {
            insv = 0.f; subv = 0.f;
        }
    }

    const int base  = (i*SYv + j)*Bv + b;
    const int plane = SXv*SYv*Bv;
    out[0*plane + base] = insv;
    out[1*plane + base] = subv;
    out[2*plane + base] = endv;
    out[3*plane + base] = dlt;
}

// ---------------- launch ----------------
extern "C" void kernel_launch(void* const* d_in, const int* in_sizes, int n_in,
                              void* d_out, int out_size)
{
    const float* sources = (const float*)d_in[0];
    const float* targets = (const float*)d_in[1];
    const float* Wih_f = (const float*)d_in[2];
    const float* Whh_f = (const float*)d_in[3];
    const float* b_f   = (const float*)d_in[4];
    const float* Wih_r = (const float*)d_in[5];
    const float* Whh_r = (const float*)d_in[6];
    const float* b_r   = (const float*)d_in[7];
    const float* Wih_m = (const float*)d_in[8];
    const float* Whh_m = (const float*)d_in[9];
    const float* b_m   = (const float*)d_in[10];
    const float* W_sub = (const float*)d_in[11];
    const float* b_sub = (const float*)d_in[12];
    const float* W_ins = (const float*)d_in[13];
    const float* b_ins = (const float*)d_in[14];
    float* out = (float*)d_out;

    const int dyn = 2 * STG * 128 * 40 * (int)sizeof(__nv_bfloat16);   // 81920 B
    cudaFuncSetAttribute(lstm_step_mma, cudaFuncAttributeMaxDynamicSharedMemorySize, dyn);

    init_misc<<<512, 512>>>(sources, targets);
    convert_weights<<<2048, 512>>>(Wih_f, Whh_f, b_f, Wih_r, Whh_r, b_r,
                                   Wih_m, Whh_m, b_m, W_sub, b_sub, W_ins, b_ins);
    for (int t = 0; t < SXv; t++)
        lstm_step_mma<<<128, 512, dyn>>>(t);
    heads_mma<<<dim3(SXv, 2, 2), 288>>>();
    pairs_kernel<<<SXv*SYv, 256>>>(out);
}

// round 11
// speedup vs baseline: 9.9696x; 1.1014x over previous
#include <cuda_runtime.h>
#include <cuda_bf16.h>
#include <math.h>
#include <stdint.h>

#define Bv   256
#define SXv  34
#define SYv  34
#define H1   512
#define H2   1024
#define IND  66
#define OD   65
#define VV   64
#define BIG_NEG -1000000000.0f

// K-extended widths (HID + 128 ext: 66 onehot + 1 bias + zero pad)
#define KEF  640
#define KEM  1152
#define KEH  1056
#define NF_  (16*128*KEF)
#define NM_  (32*128*KEM)
#define NH_  (144*KEH)

#define CSTR 72                  // smem row stride (64 + 8 pad) in bf16
#define MATEL (128*CSTR)         // 9216 el per matrix
#define STGEL (2*MATEL)          // A + B per stage
#define STGB  (STGEL*2)          // bytes per stage = 36864

// ---------------- device scratch ----------------
__device__ __align__(256) __nv_bfloat16 g_WpF[NF_];
__device__ __align__(256) __nv_bfloat16 g_WpR[NF_];
__device__ __align__(256) __nv_bfloat16 g_WpM[NM_];
__device__ __align__(256) __nv_bfloat16 g_WpH[NH_];
__device__ __align__(256) __nv_bfloat16 g_xemb[SXv][Bv][2*H1];
__device__ __align__(256) __nv_bfloat16 g_yemb[SYv][Bv][H2];
__device__ float g_cf[Bv][H1];
__device__ float g_cr[Bv][H1];
__device__ float g_cm[Bv][H2];
__device__ int   g_toks[SXv][Bv];
__device__ int   g_tokt[SYv][Bv];
__device__ float g_lx[2][SXv][OD][Bv];
__device__ float g_ly[2][SYv][OD][Bv];

__device__ __forceinline__ float sigm(float x){ return 1.0f/(1.0f+expf(-x)); }

#define LDM_X4(r0,r1,r2,r3,addr) \
    asm volatile("ldmatrix.sync.aligned.m8n8.x4.shared.b16 {%0,%1,%2,%3},[%4];" \
        : "=r"(r0),"=r"(r1),"=r"(r2),"=r"(r3) : "r"(addr))

#define MMA16816(d,a0,a1,a2,a3,b0,b1) \
    asm volatile("mma.sync.aligned.m16n8k16.row.col.f32.bf16.bf16.f32 " \
        "{%0,%1,%2,%3},{%4,%5,%6,%7},{%8,%9},{%0,%1,%2,%3};" \
        : "+f"(d[0]),"+f"(d[1]),"+f"(d[2]),"+f"(d[3]) \
        : "r"(a0),"r"(a1),"r"(a2),"r"(a3),"r"(b0),"r"(b1))

#define CP16(dst,src) \
    asm volatile("cp.async.cg.shared.global [%0],[%1],16;" :: "r"(dst),"l"(src))
#define CP_COMMIT() asm volatile("cp.async.commit_group;" ::: "memory")

// ---------------- init ----------------
__global__ void init_misc(const float* __restrict__ src, const float* __restrict__ tgt)
{
    int id = blockIdx.x * blockDim.x + threadIdx.x;
    if (id < Bv*H1) { ((float*)g_cf)[id] = 0.f; ((float*)g_cr)[id] = 0.f; }
    ((float*)g_cm)[id] = 0.f;
    if (id < SXv*Bv) {
        const float* p = src + (long)id * IND;
        int tok = -1;
        #pragma unroll 1
        for (int v = 0; v < IND; v++) if (p[v] > 0.5f) tok = v;
        ((int*)g_toks)[id] = tok;
        const float* q = tgt + (long)id * IND;
        tok = -1;
        #pragma unroll 1
        for (int v = 0; v < IND; v++) if (q[v] > 0.5f) tok = v;
        ((int*)g_tokt)[id] = tok;
    }
}

// ---------------- weight convert + permute to bf16 ----------------
// perm row lr = wm*32 + mf*16 + hi*8 + x; gate q = mf*2+hi, unit = tile*32 + wm*8 + x
__global__ void convert_weights(
    const float* __restrict__ WihF, const float* __restrict__ WhhF, const float* __restrict__ bF,
    const float* __restrict__ WihR, const float* __restrict__ WhhR, const float* __restrict__ bR,
    const float* __restrict__ WihM, const float* __restrict__ WhhM, const float* __restrict__ bM,
    const float* __restrict__ Wsub, const float* __restrict__ bsub,
    const float* __restrict__ Wins, const float* __restrict__ bins)
{
    const long total = 2L*NF_ + NM_ + NH_;
    for (long id = (long)blockIdx.x*blockDim.x + threadIdx.x; id < total;
         id += (long)gridDim.x*blockDim.x) {
        long r = id;
        if (r < 2L*NF_) {
            int which = (r >= NF_);
            long q = r - (long)which*NF_;
            int tile = (int)(q / (128*KEF));
            int rem  = (int)(q % (128*KEF));
            int lr = rem / KEF, k = rem % KEF;
            int wm = lr>>5, mf = (lr>>4)&1, hi = (lr>>3)&1, x = lr&7;
            int grow = (mf*2+hi)*H1 + tile*32 + wm*8 + x;
            const float* Whh = which ? WhhR : WhhF;
            const float* Wih = which ? WihR : WihF;
            const float* bb  = which ? bR   : bF;
            float v;
            if (k < H1) v = Whh[(long)grow*H1 + k];
            else { int c = k - H1; v = (c < IND) ? Wih[grow*IND + c] : (c == IND ? bb[grow] : 0.f); }
            (which ? g_WpR : g_WpF)[q] = __float2bfloat16(v);
        } else if ((r -= 2L*NF_) < NM_) {
            int tile = (int)(r / (128*KEM));
            int rem  = (int)(r % (128*KEM));
            int lr = rem / KEM, k = rem % KEM;
            int wm = lr>>5, mf = (lr>>4)&1, hi = (lr>>3)&1, x = lr&7;
            int grow = (mf*2+hi)*H2 + tile*32 + wm*8 + x;
            float v;
            if (k < H2) v = WhhM[(long)grow*H2 + k];
            else { int c = k - H2; v = (c < IND) ? WihM[grow*IND + c] : (c == IND ? bM[grow] : 0.f); }
            g_WpM[r] = __float2bfloat16(v);
        } else {
            r -= NM_;
            int o = (int)(r / KEH), k = (int)(r % KEH);
            float v = 0.f;
            if (o < OD)        v = (k < H2) ? Wsub[(long)o*H2 + k]      : (k == H2 ? bsub[o]    : 0.f);
            else if (o < 2*OD) v = (k < H2) ? Wins[(long)(o-OD)*H2 + k] : (k == H2 ? bins[o-OD] : 0.f);
            g_WpH[r] = __float2bfloat16(v);
        }
    }
}

// ---------------- fused 3-LSTM step: 512 threads, K=64 chunks, 3-stage cp.async ----
// 128 blocks: [0,32) fwd, [32,64) rev, [64,128) modern. Tile 128 gate-rows x 128 batch.
__global__ __launch_bounds__(512) void lstm_step_mma(int t)
{
    extern __shared__ __nv_bfloat16 dynS[];   // [3 stages][A 128x72 | B 128x72]
    __shared__ int tokS[128];

    const int tid = threadIdx.x;
    int blk = blockIdx.x;

    const __nv_bfloat16 *Wp, *Bsrc = 0;
    __nv_bfloat16 *embout;
    float *cbuf;
    const int *tokp;
    int HIDk, KE, nreg, CH, h0, boff, ooff, b0g;

    if (blk < 32) {
        int tile = blk >> 1, bh = blk & 1;
        Wp = g_WpF + (size_t)tile*128*KEF; KE = KEF; HIDk = H1; nreg = 8; CH = 10;
        h0 = tile*32; b0g = bh*128;
        if (t > 0) Bsrc = &g_xemb[t-1][0][0];
        boff = 0; tokp = &g_toks[t][0]; cbuf = &g_cf[0][0];
        embout = &g_xemb[t][0][0]; ooff = 0;
    } else if (blk < 64) {
        int tile = (blk-32) >> 1, bh = (blk-32) & 1;
        Wp = g_WpR + (size_t)tile*128*KEF; KE = KEF; HIDk = H1; nreg = 8; CH = 10;
        h0 = tile*32; b0g = bh*128;
        if (t > 0) Bsrc = &g_xemb[SXv-t][0][0];
        boff = H1; tokp = &g_toks[SXv-1-t][0]; cbuf = &g_cr[0][0];
        embout = &g_xemb[SXv-1-t][0][0]; ooff = H1;
    } else {
        int tile = (blk-64) >> 1, bh = (blk-64) & 1;
        Wp = g_WpM + (size_t)tile*128*KEM; KE = KEM; HIDk = H2; nreg = 16; CH = 18;
        h0 = tile*32; b0g = bh*128;
        if (t > 0) Bsrc = &g_yemb[t-1][0][0];
        boff = 0; tokp = &g_tokt[t][0]; cbuf = &g_cm[0][0];
        embout = &g_yemb[t][0][0]; ooff = 0;
    }

    if (tid < 128) tokS[tid] = tokp[b0g + tid];
    __syncthreads();

    const int lane = tid & 31, warp = tid >> 5;
    const int wm = warp >> 2, wn = warp & 3;

    const unsigned base_u = (unsigned)__cvta_generic_to_shared(&dynS[0]);
    const __nv_bfloat16 bfone = __float2bfloat16(1.f);
    const __nv_bfloat16 bfzero = __float2bfloat16(0.f);

    // stage chunk c (global chunk idx) into slot s
    #define STAGE(c, s) do {                                                          \
        unsigned ab_ = base_u + (unsigned)((s)*STGB);                                 \
        unsigned bb_ = ab_ + (unsigned)(MATEL*2);                                     \
        _Pragma("unroll")                                                             \
        for (int s2_ = 0; s2_ < 2; s2_++) {                                           \
            int u_ = tid*2 + s2_;                                                     \
            int row_ = u_ >> 3, kq_ = u_ & 7;                                         \
            CP16(ab_ + (unsigned)((row_*CSTR + kq_*8) << 1),                          \
                 Wp + (size_t)row_*KE + (c)*64 + kq_*8);                              \
        }                                                                             \
        if ((c) < nreg) {                                                             \
            _Pragma("unroll")                                                         \
            for (int s2_ = 0; s2_ < 2; s2_++) {                                       \
                int u_ = tid*2 + s2_;                                                 \
                int row_ = u_ >> 3, kq_ = u_ & 7;                                     \
                CP16(bb_ + (unsigned)((row_*CSTR + kq_*8) << 1),                      \
                     Bsrc + (size_t)(b0g+row_)*1024 + boff + (c)*64 + kq_*8);         \
            }                                                                         \
        } else {                                                                      \
            int kbase_ = ((c) - nreg) * 64;                                           \
            __nv_bfloat16* bs_ = dynS + (s)*STGEL + MATEL;                            \
            _Pragma("unroll")                                                         \
            for (int s2_ = 0; s2_ < 16; s2_++) {                                      \
                int idx_ = tid + s2_*512;                                             \
                int n_ = idx_ >> 6, kk_ = idx_ & 63;                                  \
                int v_ = kbase_ + kk_;                                                \
                bs_[n_*CSTR + kk_] = (v_ == tokS[n_] || v_ == IND) ? bfone : bfzero;  \
            }                                                                         \
        }                                                                             \
        CP_COMMIT();                                                                  \
    } while (0)

    float acc[2][4][4];
    #pragma unroll
    for (int a = 0; a < 2; a++)
        #pragma unroll
        for (int b = 0; b < 4; b++)
            #pragma unroll
            for (int c = 0; c < 4; c++) acc[a][b][c] = 0.f;

    const int cf   = (t == 0) ? nreg : 0;
    const int nIss = CH - cf;

    STAGE(cf, 0);
    if (nIss > 1) STAGE(cf + 1, 1);

    for (int ci = 0; ci < nIss; ci++) {
        if (ci < nIss - 1) asm volatile("cp.async.wait_group 1;" ::: "memory");
        else               asm volatile("cp.async.wait_group 0;" ::: "memory");
        __syncthreads();
        if (ci + 2 < nIss) { int cn = ci + 2; int sl = cn % 3; STAGE(cf + cn, sl); }

        const int p = ci % 3;
        const unsigned asb = base_u + (unsigned)(p*STGB);
        const unsigned bsb = asb + (unsigned)(MATEL*2);

        #pragma unroll
        for (int k16 = 0; k16 < 4; k16++) {
            unsigned a[2][4];
            #pragma unroll
            for (int mf = 0; mf < 2; mf++) {
                unsigned addr = asb + (unsigned)((((wm*32 + mf*16 + (lane & 15))*CSTR)
                                + k16*16 + ((lane >> 4) << 3)) << 1);
                LDM_X4(a[mf][0], a[mf][1], a[mf][2], a[mf][3], addr);
            }
            unsigned bf[2][4];
            #pragma unroll
            for (int pr = 0; pr < 2; pr++) {
                int row = wn*32 + pr*16 + ((lane >> 4) << 3) + (lane & 7);
                int col = k16*16 + (((lane >> 3) & 1) << 3);
                unsigned addr = bsb + (unsigned)((row*CSTR + col) << 1);
                LDM_X4(bf[pr][0], bf[pr][1], bf[pr][2], bf[pr][3], addr);
            }
            #pragma unroll
            for (int mf = 0; mf < 2; mf++)
                #pragma unroll
                for (int nf = 0; nf < 4; nf++)
                    MMA16816(acc[mf][nf], a[mf][0], a[mf][1], a[mf][2], a[mf][3],
                             bf[nf>>1][(nf&1)*2], bf[nf>>1][(nf&1)*2+1]);
        }
    }

    // epilogue: all 4 gates of unit (h0 + wm*8 + lane>>2) in-thread
    const int x4 = lane >> 2, tig = lane & 3;
    const int unit = h0 + wm*8 + x4;
    #pragma unroll
    for (int nf = 0; nf < 4; nf++) {
        #pragma unroll
        for (int cc = 0; cc < 2; cc++) {
            const int b = b0g + wn*32 + nf*8 + 2*tig + cc;
            float gi = acc[0][nf][cc];
            float gf = acc[0][nf][2+cc];
            float gg = acc[1][nf][cc];
            float go = acc[1][nf][2+cc];
            float cold = cbuf[(size_t)b*HIDk + unit];
            float cn = sigm(gf)*cold + sigm(gi)*tanhf(gg);
            float hn = sigm(go)*tanhf(cn);
            cbuf[(size_t)b*HIDk + unit] = cn;
            embout[(size_t)b*1024 + ooff + unit] = __float2bfloat16(hn);
        }
    }
    #undef STAGE
}

// ---------------- heads via mma.sync bf16 ----------------
__global__ __launch_bounds__(288) void heads_mma()
{
    __shared__ __nv_bfloat16 As[2][144][40];
    __shared__ __nv_bfloat16 Bs[2][128][40];

    const int i = blockIdx.x, ss = blockIdx.y, bh = blockIdx.z;
    const int tid = threadIdx.x;
    const __nv_bfloat16* Bsrc = ss ? &g_yemb[i][0][0] : &g_xemb[i][0][0];
    const int b0g = bh * 128;
    const int nch = 32 + ss;

    const int lane = tid & 31, w = tid >> 5;

    float acc[16][4];
    #pragma unroll
    for (int nf = 0; nf < 16; nf++)
        #pragma unroll
        for (int c = 0; c < 4; c++) acc[nf][c] = 0.f;

    {
        #pragma unroll
        for (int s = 0; s < 2; s++) {
            int u = tid*2 + s, row = u >> 2, kq = u & 3;
            *(uint4*)&As[0][row][kq*8] = *(const uint4*)(g_WpH + (size_t)row*KEH + kq*8);
        }
        #pragma unroll
        for (int s = 0; s < 2; s++) {
            int u = tid + s*288;
            if (u < 512) {
                int row = u >> 2, kq = u & 3;
                *(uint4*)&Bs[0][row][kq*8] = *(const uint4*)(Bsrc + (size_t)(b0g+row)*1024 + kq*8);
            }
        }
    }

    for (int ch = 0; ch < nch; ch++) {
        const int p = ch & 1;
        __syncthreads();
        if (ch + 1 < nch) {
            const int cn = ch + 1, pa = p ^ 1;
            #pragma unroll
            for (int s = 0; s < 2; s++) {
                int u = tid*2 + s, row = u >> 2, kq = u & 3;
                *(uint4*)&As[pa][row][kq*8] = *(const uint4*)(g_WpH + (size_t)row*KEH + cn*32 + kq*8);
            }
            if (cn < 32) {
                #pragma unroll
                for (int s = 0; s < 2; s++) {
                    int u = tid + s*288;
                    if (u < 512) {
                        int row = u >> 2, kq = u & 3;
                        *(uint4*)&Bs[pa][row][kq*8] =
                            *(const uint4*)(Bsrc + (size_t)(b0g+row)*1024 + cn*32 + kq*8);
                    }
                }
            } else {
                #pragma unroll
                for (int s = 0; s < 15; s++) {
                    int idx = tid + s*288;
                    if (idx < 4096) {
                        int n = idx >> 5, kk = idx & 31;
                        Bs[pa][n][kk] = __float2bfloat16(kk == 0 ? 1.f : 0.f);
                    }
                }
            }
        }
        const unsigned asb = (unsigned)__cvta_generic_to_shared(&As[p][0][0]);
        #pragma unroll
        for (int h16 = 0; h16 < 2; h16++) {
            unsigned a[4];
            unsigned addr = asb + (((w*16 + (lane & 15))*40 + h16*16 + ((lane >> 4) << 3)) << 1);
            LDM_X4(a[0], a[1], a[2], a[3], addr);
            #pragma unroll
            for (int nf = 0; nf < 16; nf++) {
                unsigned b0, b1;
                const __nv_bfloat16* bp = &Bs[p][nf*8 + (lane >> 2)][h16*16 + 2*(lane & 3)];
                b0 = *(const unsigned*)bp;
                b1 = *(const unsigned*)(bp + 8);
                MMA16816(acc[nf], a[0], a[1], a[2], a[3], b0, b1);
            }
        }
    }

    const int x = lane >> 2, cp = lane & 3;
    #pragma unroll
    for (int hi = 0; hi < 2; hi++) {
        const int op = w*16 + hi*8 + x;
        if (op < 2*OD) {
            const int head = (op >= OD);
            const int oo = op - head*OD;
            float* dst = ss ? &g_ly[head][i][oo][0] : &g_lx[head][i][oo][0];
            #pragma unroll
            for (int nf = 0; nf < 16; nf++) {
                #pragma unroll
                for (int cc = 0; cc < 2; cc++) {
                    const int b = b0g + nf*8 + 2*cp + cc;
                    dst[b] = acc[nf][hi*2 + cc];
                }
            }
        }
    }
}

// ---------------- pair logsumexp + masked gathers -> output ----------------
__global__ __launch_bounds__(256) void pairs_kernel(float* __restrict__ out)
{
    const int i = blockIdx.x / SYv;
    const int j = blockIdx.x % SYv;
    const int b = threadIdx.x;

    const bool x_any = g_toks[i][b] >= 0;
    const bool y_any = g_tokt[j][b] >= 0;
    const bool valid = x_any && y_any && (j < SYv-1);
    const int tnext = (j+1 < SYv) ? g_tokt[j+1][b] : -1;
    const bool ins_ok = valid && (tnext != IND-1);

    const float* lx0 = &g_lx[0][i][0][0];
    const float* lx1 = &g_lx[1][i][0][0];
    const float* ly0 = &g_ly[0][j][0][0];
    const float* ly1 = &g_ly[1][j][0][0];

    float m0 = -1e30f, s0 = 0.f, m1 = -1e30f, s1 = 0.f;
    #pragma unroll 1
    for (int o = 0; o < OD; o++) {
        float z0 = lx0[o*Bv+b] + ly0[o*Bv+b];
        float nm0 = fmaxf(m0, z0);
        s0 = s0*__expf(m0-nm0) + __expf(z0-nm0);
        m0 = nm0;
        float z1 = lx1[o*Bv+b] + ly1[o*Bv+b];
        float nm1 = fmaxf(m1, z1);
        s1 = s1*__expf(m1-nm1) + __expf(z1-nm1);
        m1 = nm1;
    }
    const float lse0 = m0 + __logf(s0);
    const float lse1 = m1 + __logf(s1);

    float dlt  = valid ? (lx0[VV*Bv+b] + ly0[VV*Bv+b] - lse0) : BIG_NEG;
    float endv = valid ? (lx1[VV*Bv+b] + ly1[VV*Bv+b] - lse1) : BIG_NEG;
    float insv = BIG_NEG, subv = BIG_NEG;
    if (ins_ok) {
        if (tnext >= 0 && tnext < VV) {
            subv = lx0[tnext*Bv+b] + ly0[tnext*Bv+b] - lse0;
            insv = lx1[tnext*Bv+b] + ly1[tnext*Bv+b] - lse1;
        } else {
            insv = 0.f; subv = 0.f;
        }
    }

    const int base  = (i*SYv + j)*Bv + b;
    const int plane = SXv*SYv*Bv;
    out[0*plane + base] = insv;
    out[1*plane + base] = subv;
    out[2*plane + base] = endv;
    out[3*plane + base] = dlt;
}

// ---------------- launch ----------------
extern "C" void kernel_launch(void* const* d_in, const int* in_sizes, int n_in,
                              void* d_out, int out_size)
{
    const float* sources = (const float*)d_in[0];
    const float* targets = (const float*)d_in[1];
    const float* Wih_f = (const float*)d_in[2];
    const float* Whh_f = (const float*)d_in[3];
    const float* b_f   = (const float*)d_in[4];
    const float* Wih_r = (const float*)d_in[5];
    const float* Whh_r = (const float*)d_in[6];
    const float* b_r   = (const float*)d_in[7];
    const float* Wih_m = (const float*)d_in[8];
    const float* Whh_m = (const float*)d_in[9];
    const float* b_m   = (const float*)d_in[10];
    const float* W_sub = (const float*)d_in[11];
    const float* b_sub = (const float*)d_in[12];
    const float* W_ins = (const float*)d_in[13];
    const float* b_ins = (const float*)d_in[14];
    float* out = (float*)d_out;

    const int dyn = 3 * STGB;   // 110592 B
    cudaFuncSetAttribute(lstm_step_mma, cudaFuncAttributeMaxDynamicSharedMemorySize, dyn);

    init_misc<<<512, 512>>>(sources, targets);
    convert_weights<<<2048, 512>>>(Wih_f, Whh_f, b_f, Wih_r, Whh_r, b_r,
                                   Wih_m, Whh_m, b_m, W_sub, b_sub, W_ins, b_ins);
    for (int t = 0; t < SXv; t++)
        lstm_step_mma<<<128, 512, dyn>>>(t);
    heads_mma<<<dim3(SXv, 2, 2), 288>>>();
    pairs_kernel<<<SXv*SYv, 256>>>(out);
}